// round 4
// baseline (speedup 1.0000x reference)
#include <cuda_runtime.h>
#include <stdint.h>

#define N_NODES 50000
#define N_EDGES 800000
#define IN_F    256
#define OUT_F   64

typedef unsigned long long ull;

// Scratch for h = x @ W  (50000 x 64 fp32 = 12.8 MB) — device global (no allocs allowed)
__device__ float g_h[N_NODES * OUT_F];

// ---------------------------------------------------------------------------
// Kernel 1: h = x @ W  — FMA2 SGEMM, occupancy-tuned.
//   BM=128 x BN=64, BK=16. 256 threads, each owns 8 rows x 4 cols.
//   Row-pair accumulators in f32x2; A pairs come packed from xs (transposed),
//   B values stored PRE-DUPLICATED as (b,b) ull in ws2 -> no packing MOVs in
//   the inner loop. Double-buffered, one __syncthreads per k-tile.
// ---------------------------------------------------------------------------
#define BM 128
#define BN 64
#define BK 16
#define XS_STRIDE (BM + 4)     // 132 floats; k-row = 528 B, 16B-aligned slices

__global__ void __launch_bounds__(256, 3) gemm_kernel(
    const float* __restrict__ x, const float* __restrict__ w)
{
    __shared__ __align__(16) float xs[2][BK][XS_STRIDE];  // x tile transposed: xs[k][m]
    __shared__ __align__(16) ull   ws2[2][BK][BN];        // w tile, each value duplicated (b,b)

    const int tid = threadIdx.x;
    const int tx = tid & 15;          // n0 = tx*4
    const int ty = tid >> 4;          // m0 = ty*8
    const int m0 = ty * 8, n0 = tx * 4;
    const int block_m = blockIdx.x * BM;

    // ---- x-tile loader: 128x16 floats = 512 float4; 2 per thread ----
    const int xrow = tid >> 2;               // 0..63
    const int xkc  = (tid & 3) << 2;         // 0,4,8,12
    const int gr0 = min(block_m + xrow,      N_NODES - 1);
    const int gr1 = min(block_m + xrow + 64, N_NODES - 1);
    const float* xp0 = x + (size_t)gr0 * IN_F + xkc;
    const float* xp1 = x + (size_t)gr1 * IN_F + xkc;

    // ---- w-tile loader: 16x64 floats = 256 float4; 1 per thread ----
    const int wrow = tid >> 4;               // 0..15 (k within tile)
    const int wcol = (tid & 15) << 2;        // 0..60 step 4
    const float* wp = w + (size_t)wrow * OUT_F + wcol;

    ull acc[4][4];
    #pragma unroll
    for (int i = 0; i < 4; i++)
        #pragma unroll
        for (int j = 0; j < 4; j++) acc[i][j] = 0ull;

    // ---- prologue: fetch tile 0, stage into buffer 0 ----
    float4 xf0 = *(const float4*)xp0;
    float4 xf1 = *(const float4*)xp1;
    float4 wf  = *(const float4*)wp;

    {
        xs[0][xkc + 0][xrow] = xf0.x; xs[0][xkc + 1][xrow] = xf0.y;
        xs[0][xkc + 2][xrow] = xf0.z; xs[0][xkc + 3][xrow] = xf0.w;
        xs[0][xkc + 0][xrow + 64] = xf1.x; xs[0][xkc + 1][xrow + 64] = xf1.y;
        xs[0][xkc + 2][xrow + 64] = xf1.z; xs[0][xkc + 3][xrow + 64] = xf1.w;
        ull d0, d1, d2, d3;
        asm("mov.b64 %0, {%1, %1};" : "=l"(d0) : "r"(__float_as_uint(wf.x)));
        asm("mov.b64 %0, {%1, %1};" : "=l"(d1) : "r"(__float_as_uint(wf.y)));
        asm("mov.b64 %0, {%1, %1};" : "=l"(d2) : "r"(__float_as_uint(wf.z)));
        asm("mov.b64 %0, {%1, %1};" : "=l"(d3) : "r"(__float_as_uint(wf.w)));
        ws2[0][wrow][wcol + 0] = d0; ws2[0][wrow][wcol + 1] = d1;
        ws2[0][wrow][wcol + 2] = d2; ws2[0][wrow][wcol + 3] = d3;
    }
    __syncthreads();

    const int NKT = IN_F / BK;   // 16 k-tiles

    #pragma unroll 1
    for (int kt = 0; kt < NKT; kt++) {
        const int buf = kt & 1;

        // prefetch next tile global -> registers
        if (kt + 1 < NKT) {
            const int k0 = (kt + 1) * BK;
            xf0 = *(const float4*)(xp0 + k0);
            xf1 = *(const float4*)(xp1 + k0);
            wf  = *(const float4*)(wp + (size_t)k0 * OUT_F);
        }

        // ---- compute on current buffer: 4 LDS.128 + 16 FMA2 per k ----
        #pragma unroll
        for (int k = 0; k < BK; k++) {
            const double2 av0 = *(const double2*)&xs[buf][k][m0];
            const double2 av1 = *(const double2*)&xs[buf][k][m0 + 4];
            ull a2[4];
            a2[0] = __double_as_longlong(av0.x);
            a2[1] = __double_as_longlong(av0.y);
            a2[2] = __double_as_longlong(av1.x);
            a2[3] = __double_as_longlong(av1.y);

            const ulonglong2 bv0 = *(const ulonglong2*)&ws2[buf][k][n0];
            const ulonglong2 bv1 = *(const ulonglong2*)&ws2[buf][k][n0 + 2];
            ull b2[4] = {bv0.x, bv0.y, bv1.x, bv1.y};

            #pragma unroll
            for (int j = 0; j < 4; j++)
                #pragma unroll
                for (int i = 0; i < 4; i++)
                    asm("fma.rn.f32x2 %0, %1, %2, %0;"
                        : "+l"(acc[i][j]) : "l"(a2[i]), "l"(b2[j]));
        }

        // stage prefetched tile into other buffer
        if (kt + 1 < NKT) {
            const int nb = buf ^ 1;
            xs[nb][xkc + 0][xrow] = xf0.x; xs[nb][xkc + 1][xrow] = xf0.y;
            xs[nb][xkc + 2][xrow] = xf0.z; xs[nb][xkc + 3][xrow] = xf0.w;
            xs[nb][xkc + 0][xrow + 64] = xf1.x; xs[nb][xkc + 1][xrow + 64] = xf1.y;
            xs[nb][xkc + 2][xrow + 64] = xf1.z; xs[nb][xkc + 3][xrow + 64] = xf1.w;
            ull d0, d1, d2, d3;
            asm("mov.b64 %0, {%1, %1};" : "=l"(d0) : "r"(__float_as_uint(wf.x)));
            asm("mov.b64 %0, {%1, %1};" : "=l"(d1) : "r"(__float_as_uint(wf.y)));
            asm("mov.b64 %0, {%1, %1};" : "=l"(d2) : "r"(__float_as_uint(wf.z)));
            asm("mov.b64 %0, {%1, %1};" : "=l"(d3) : "r"(__float_as_uint(wf.w)));
            ws2[nb][wrow][wcol + 0] = d0; ws2[nb][wrow][wcol + 1] = d1;
            ws2[nb][wrow][wcol + 2] = d2; ws2[nb][wrow][wcol + 3] = d3;
            __syncthreads();
        }
    }

    // ---- epilogue: unpack row pairs, store 8 rows x 4 cols ----
    #pragma unroll
    for (int i = 0; i < 4; i++) {
        unsigned lo[4], hi[4];
        #pragma unroll
        for (int j = 0; j < 4; j++)
            asm("mov.b64 {%0, %1}, %2;" : "=r"(lo[j]), "=r"(hi[j]) : "l"(acc[i][j]));
        const int r0 = block_m + m0 + 2 * i;
        if (r0 < N_NODES)
            *(float4*)(g_h + (size_t)r0 * OUT_F + n0) =
                make_float4(__uint_as_float(lo[0]), __uint_as_float(lo[1]),
                            __uint_as_float(lo[2]), __uint_as_float(lo[3]));
        if (r0 + 1 < N_NODES)
            *(float4*)(g_h + (size_t)(r0 + 1) * OUT_F + n0) =
                make_float4(__uint_as_float(hi[0]), __uint_as_float(hi[1]),
                            __uint_as_float(hi[2]), __uint_as_float(hi[3]));
    }
}

// ---------------------------------------------------------------------------
// Kernel 2: out[n][f] = bias[f]   (out is poisoned; must init before atomics)
// ---------------------------------------------------------------------------
__global__ void init_kernel(float* __restrict__ out, const float* __restrict__ bias)
{
    const int t = blockIdx.x * blockDim.x + threadIdx.x;
    const int total4 = N_NODES * OUT_F / 4;
    if (t < total4) {
        const float4* b4 = (const float4*)bias;
        ((float4*)out)[t] = __ldg(&b4[t & 15]);
    }
}

// ---------------------------------------------------------------------------
// Kernel 3: scatter — out[dst] += w_e * h[src].  16 threads per edge,
// each thread does one float4 slice via red.global.add.v4.f32 (sm_90+).
// ---------------------------------------------------------------------------
__global__ void scatter_kernel(const float* __restrict__ ew,
                               const int* __restrict__ esrc,
                               const int* __restrict__ edst,
                               float* __restrict__ out)
{
    const int t = blockIdx.x * blockDim.x + threadIdx.x;
    const int e = t >> 4;
    if (e >= N_EDGES) return;
    const int c = (t & 15) << 2;

    const int src = __ldg(&esrc[e]);
    const int dst = __ldg(&edst[e]);
    const float w = __ldg(&ew[e]);

    const float4 hv = *(const float4*)(g_h + (size_t)src * OUT_F + c);
    float* p = out + (size_t)dst * OUT_F + c;
    asm volatile("red.global.add.v4.f32 [%0], {%1, %2, %3, %4};"
                 :: "l"(p), "f"(hv.x * w), "f"(hv.y * w), "f"(hv.z * w), "f"(hv.w * w)
                 : "memory");
}

// ---------------------------------------------------------------------------
// inputs (metadata order): x, weight, bias, edge_weight, edge_src, edge_dst
// ---------------------------------------------------------------------------
extern "C" void kernel_launch(void* const* d_in, const int* in_sizes, int n_in,
                              void* d_out, int out_size)
{
    const float* x      = (const float*)d_in[0];
    const float* weight = (const float*)d_in[1];
    const float* bias   = (const float*)d_in[2];
    const float* ew     = (const float*)d_in[3];
    const int*   esrc   = (const int*)d_in[4];
    const int*   edst   = (const int*)d_in[5];
    float* out = (float*)d_out;

    // 1) h = x @ W   (FMA2 register-blocked SGEMM)
    {
        const int grid = (N_NODES + BM - 1) / BM;   // 391
        gemm_kernel<<<grid, 256>>>(x, weight);
    }

    // 2) out = bias
    {
        const int total4 = N_NODES * OUT_F / 4;
        init_kernel<<<(total4 + 255) / 256, 256>>>(out, bias);
    }

    // 3) scatter-add over edges
    {
        const long long threads = (long long)N_EDGES * 16;
        const int blk = 256;
        const int grid = (int)((threads + blk - 1) / blk);
        scatter_kernel<<<grid, blk>>>(ew, esrc, edst, out);
    }
}

// round 6
// speedup vs baseline: 1.7861x; 1.7861x over previous
#include <cuda_runtime.h>
#include <stdint.h>

#define N_NODES 50000
#define N_EDGES 800000
#define IN_F    256
#define OUT_F   64

// Scratch for h = x @ W  (50000 x 64 fp32 = 12.8 MB) — device global (no allocs allowed)
__device__ float g_h[N_NODES * OUT_F];

__device__ __forceinline__ uint32_t f2tf(float f) {
    uint32_t r;
    asm("cvt.rna.tf32.f32 %0, %1;" : "=r"(r) : "f"(f));
    return r;
}

// ---------------------------------------------------------------------------
// Kernel 1: h = x @ W via warp-level mma.sync tf32 (m16n8k8).
//   BM=128, BN=64, BK=16, 256 threads = 8 warps.
//   Warp grid: 4 warp-rows x 2 warp-cols; each warp owns 32 rows x 32 cols
//   = 2 m-tiles x 4 n-tiles. Double-buffered smem, strides chosen so all
//   fragment LDS.32 patterns are bank-conflict-free (xs stride 20, ws stride 72).
// ---------------------------------------------------------------------------
#define BM 128
#define BK 16
#define XS_STR 20
#define WS_STR 72

__global__ void __launch_bounds__(256, 3) gemm_kernel(
    const float* __restrict__ x, const float* __restrict__ w)
{
    __shared__ __align__(16) uint32_t xs[2][BM][XS_STR];  // A tile (tf32 bits), [row][k]
    __shared__ __align__(16) uint32_t ws[2][BK][WS_STR];  // W tile (tf32 bits), [k][n]

    const int tid  = threadIdx.x;
    const int wid  = tid >> 5;
    const int lane = tid & 31;
    const int wm = wid >> 1;          // warp-row 0..3  -> rows wm*32..wm*32+31
    const int wn = wid & 1;           // warp-col 0..1  -> cols wn*32..wn*32+31
    const int g  = lane >> 2;         // group id 0..7
    const int q  = lane & 3;          // thread-in-group 0..3
    const int block_m = blockIdx.x * BM;

    // ---- A staging map: 512 float4 per tile, 2 per thread ----
    const int arow = tid >> 2;               // 0..63 (and +64)
    const int akl  = (tid & 3) << 2;         // 0,4,8,12
    const int gr0 = min(block_m + arow,      N_NODES - 1);
    const int gr1 = min(block_m + arow + 64, N_NODES - 1);
    const float* xp0 = x + (size_t)gr0 * IN_F + akl;
    const float* xp1 = x + (size_t)gr1 * IN_F + akl;

    // ---- W staging map: 256 float4 per tile, 1 per thread ----
    const int wk  = tid >> 4;                // k 0..15
    const int wn4 = (tid & 15) << 2;         // n 0..60 step 4
    const float* wp = w + (size_t)wk * OUT_F + wn4;

    float acc[2][4][4];
    #pragma unroll
    for (int i = 0; i < 2; i++)
        #pragma unroll
        for (int j = 0; j < 4; j++)
            #pragma unroll
            for (int r = 0; r < 4; r++) acc[i][j][r] = 0.f;

    // ---- prologue: fetch tile 0, stage into buffer 0 ----
    float4 xf0 = *(const float4*)xp0;
    float4 xf1 = *(const float4*)xp1;
    float4 wf  = *(const float4*)wp;

    *(uint4*)&xs[0][arow][akl]      = make_uint4(f2tf(xf0.x), f2tf(xf0.y), f2tf(xf0.z), f2tf(xf0.w));
    *(uint4*)&xs[0][arow + 64][akl] = make_uint4(f2tf(xf1.x), f2tf(xf1.y), f2tf(xf1.z), f2tf(xf1.w));
    *(uint4*)&ws[0][wk][wn4]        = make_uint4(f2tf(wf.x),  f2tf(wf.y),  f2tf(wf.z),  f2tf(wf.w));
    __syncthreads();

    const int NKT = IN_F / BK;   // 16

    #pragma unroll 1
    for (int kt = 0; kt < NKT; kt++) {
        const int buf = kt & 1;

        // prefetch next tile global -> registers
        if (kt + 1 < NKT) {
            const int k0 = (kt + 1) * BK;
            xf0 = *(const float4*)(xp0 + k0);
            xf1 = *(const float4*)(xp1 + k0);
            wf  = *(const float4*)(wp + (size_t)k0 * OUT_F);
        }

        // ---- compute: 2 k8 steps, 8 MMAs each ----
        #pragma unroll
        for (int s = 0; s < 2; s++) {
            uint32_t a[2][4], b[4][2];
            #pragma unroll
            for (int i = 0; i < 2; i++) {
                const uint32_t* xr  = &xs[buf][wm * 32 + 16 * i + g][8 * s + q];
                const uint32_t* xr8 = xr + 8 * XS_STR;
                a[i][0] = xr[0];  a[i][2] = xr[4];
                a[i][1] = xr8[0]; a[i][3] = xr8[4];
            }
            #pragma unroll
            for (int j = 0; j < 4; j++) {
                const uint32_t* wr = &ws[buf][8 * s + q][wn * 32 + 8 * j + g];
                b[j][0] = wr[0];
                b[j][1] = wr[4 * WS_STR];
            }
            #pragma unroll
            for (int i = 0; i < 2; i++)
                #pragma unroll
                for (int j = 0; j < 4; j++)
                    asm("mma.sync.aligned.m16n8k8.row.col.f32.tf32.tf32.f32 "
                        "{%0,%1,%2,%3}, {%4,%5,%6,%7}, {%8,%9}, {%0,%1,%2,%3};"
                        : "+f"(acc[i][j][0]), "+f"(acc[i][j][1]),
                          "+f"(acc[i][j][2]), "+f"(acc[i][j][3])
                        : "r"(a[i][0]), "r"(a[i][1]), "r"(a[i][2]), "r"(a[i][3]),
                          "r"(b[j][0]), "r"(b[j][1]));
        }

        // stage prefetched tile into the other buffer
        if (kt + 1 < NKT) {
            const int nb = buf ^ 1;
            *(uint4*)&xs[nb][arow][akl]      = make_uint4(f2tf(xf0.x), f2tf(xf0.y), f2tf(xf0.z), f2tf(xf0.w));
            *(uint4*)&xs[nb][arow + 64][akl] = make_uint4(f2tf(xf1.x), f2tf(xf1.y), f2tf(xf1.z), f2tf(xf1.w));
            *(uint4*)&ws[nb][wk][wn4]        = make_uint4(f2tf(wf.x),  f2tf(wf.y),  f2tf(wf.z),  f2tf(wf.w));
            __syncthreads();
        }
    }

    // ---- epilogue: store accumulators (c0,c1)/(c2,c3) as float2 ----
    #pragma unroll
    for (int i = 0; i < 2; i++) {
        const int row = block_m + wm * 32 + 16 * i + g;
        #pragma unroll
        for (int j = 0; j < 4; j++) {
            const int col = wn * 32 + 8 * j + 2 * q;
            if (row < N_NODES)
                *(float2*)(g_h + (size_t)row * OUT_F + col) =
                    make_float2(acc[i][j][0], acc[i][j][1]);
            if (row + 8 < N_NODES)
                *(float2*)(g_h + (size_t)(row + 8) * OUT_F + col) =
                    make_float2(acc[i][j][2], acc[i][j][3]);
        }
    }
}

// ---------------------------------------------------------------------------
// Kernel 2: out[n][f] = bias[f]   (out is poisoned; must init before atomics)
// ---------------------------------------------------------------------------
__global__ void init_kernel(float* __restrict__ out, const float* __restrict__ bias)
{
    const int t = blockIdx.x * blockDim.x + threadIdx.x;
    const int total4 = N_NODES * OUT_F / 4;
    if (t < total4) {
        const float4* b4 = (const float4*)bias;
        ((float4*)out)[t] = __ldg(&b4[t & 15]);
    }
}

// ---------------------------------------------------------------------------
// Kernel 3: scatter — out[dst] += w_e * h[src].  16 threads per edge,
// each thread does one float4 slice via red.global.add.v4.f32 (sm_90+).
// ---------------------------------------------------------------------------
__global__ void scatter_kernel(const float* __restrict__ ew,
                               const int* __restrict__ esrc,
                               const int* __restrict__ edst,
                               float* __restrict__ out)
{
    const int t = blockIdx.x * blockDim.x + threadIdx.x;
    const int e = t >> 4;
    if (e >= N_EDGES) return;
    const int c = (t & 15) << 2;

    const int src = __ldg(&esrc[e]);
    const int dst = __ldg(&edst[e]);
    const float w = __ldg(&ew[e]);

    const float4 hv = *(const float4*)(g_h + (size_t)src * OUT_F + c);
    float* p = out + (size_t)dst * OUT_F + c;
    asm volatile("red.global.add.v4.f32 [%0], {%1, %2, %3, %4};"
                 :: "l"(p), "f"(hv.x * w), "f"(hv.y * w), "f"(hv.z * w), "f"(hv.w * w)
                 : "memory");
}

// ---------------------------------------------------------------------------
// inputs (metadata order): x, weight, bias, edge_weight, edge_src, edge_dst
// ---------------------------------------------------------------------------
extern "C" void kernel_launch(void* const* d_in, const int* in_sizes, int n_in,
                              void* d_out, int out_size)
{
    const float* x      = (const float*)d_in[0];
    const float* weight = (const float*)d_in[1];
    const float* bias   = (const float*)d_in[2];
    const float* ew     = (const float*)d_in[3];
    const int*   esrc   = (const int*)d_in[4];
    const int*   edst   = (const int*)d_in[5];
    float* out = (float*)d_out;

    // 1) h = x @ W   (mma.sync tf32)
    {
        const int grid = (N_NODES + BM - 1) / BM;   // 391
        gemm_kernel<<<grid, 256>>>(x, weight);
    }

    // 2) out = bias
    {
        const int total4 = N_NODES * OUT_F / 4;
        init_kernel<<<(total4 + 255) / 256, 256>>>(out, bias);
    }

    // 3) scatter-add over edges
    {
        const long long threads = (long long)N_EDGES * 16;
        const int blk = 256;
        const int grid = (int)((threads + blk - 1) / blk);
        scatter_kernel<<<grid, blk>>>(ew, esrc, edst, out);
    }
}

// round 7
// speedup vs baseline: 1.9542x; 1.0941x over previous
#include <cuda_runtime.h>
#include <stdint.h>

#define N_NODES 50000
#define N_EDGES 800000
#define IN_F    256
#define OUT_F   64
#define CAP     128           // bucket capacity per node (avg degree 16)

// Device scratch (no allocs allowed)
__device__ float g_h[N_NODES * OUT_F];              // 12.8 MB: h = x @ W
__device__ int   g_cnt[N_NODES];                    // per-dst edge counts
__device__ uint2 g_bucket[(size_t)N_NODES * CAP];   // 51.2 MB: (src, w_bits)

__device__ __forceinline__ uint32_t f2tf(float f) {
    uint32_t r;
    asm("cvt.rna.tf32.f32 %0, %1;" : "=r"(r) : "f"(f));
    return r;
}

// ---------------------------------------------------------------------------
// Kernel 1: h = x @ W via warp-level mma.sync tf32 (m16n8k8).  (round-6 proven)
// ---------------------------------------------------------------------------
#define BM 128
#define BK 16
#define XS_STR 20
#define WS_STR 72

__global__ void __launch_bounds__(256, 3) gemm_kernel(
    const float* __restrict__ x, const float* __restrict__ w)
{
    __shared__ __align__(16) uint32_t xs[2][BM][XS_STR];  // A tile (tf32 bits), [row][k]
    __shared__ __align__(16) uint32_t ws[2][BK][WS_STR];  // W tile (tf32 bits), [k][n]

    const int tid  = threadIdx.x;
    const int wid  = tid >> 5;
    const int lane = tid & 31;
    const int wm = wid >> 1;
    const int wn = wid & 1;
    const int g  = lane >> 2;
    const int q  = lane & 3;
    const int block_m = blockIdx.x * BM;

    const int arow = tid >> 2;
    const int akl  = (tid & 3) << 2;
    const int gr0 = min(block_m + arow,      N_NODES - 1);
    const int gr1 = min(block_m + arow + 64, N_NODES - 1);
    const float* xp0 = x + (size_t)gr0 * IN_F + akl;
    const float* xp1 = x + (size_t)gr1 * IN_F + akl;

    const int wk  = tid >> 4;
    const int wn4 = (tid & 15) << 2;
    const float* wp = w + (size_t)wk * OUT_F + wn4;

    float acc[2][4][4];
    #pragma unroll
    for (int i = 0; i < 2; i++)
        #pragma unroll
        for (int j = 0; j < 4; j++)
            #pragma unroll
            for (int r = 0; r < 4; r++) acc[i][j][r] = 0.f;

    float4 xf0 = *(const float4*)xp0;
    float4 xf1 = *(const float4*)xp1;
    float4 wf  = *(const float4*)wp;

    *(uint4*)&xs[0][arow][akl]      = make_uint4(f2tf(xf0.x), f2tf(xf0.y), f2tf(xf0.z), f2tf(xf0.w));
    *(uint4*)&xs[0][arow + 64][akl] = make_uint4(f2tf(xf1.x), f2tf(xf1.y), f2tf(xf1.z), f2tf(xf1.w));
    *(uint4*)&ws[0][wk][wn4]        = make_uint4(f2tf(wf.x),  f2tf(wf.y),  f2tf(wf.z),  f2tf(wf.w));
    __syncthreads();

    const int NKT = IN_F / BK;

    #pragma unroll 1
    for (int kt = 0; kt < NKT; kt++) {
        const int buf = kt & 1;

        if (kt + 1 < NKT) {
            const int k0 = (kt + 1) * BK;
            xf0 = *(const float4*)(xp0 + k0);
            xf1 = *(const float4*)(xp1 + k0);
            wf  = *(const float4*)(wp + (size_t)k0 * OUT_F);
        }

        #pragma unroll
        for (int s = 0; s < 2; s++) {
            uint32_t a[2][4], b[4][2];
            #pragma unroll
            for (int i = 0; i < 2; i++) {
                const uint32_t* xr  = &xs[buf][wm * 32 + 16 * i + g][8 * s + q];
                const uint32_t* xr8 = xr + 8 * XS_STR;
                a[i][0] = xr[0];  a[i][2] = xr[4];
                a[i][1] = xr8[0]; a[i][3] = xr8[4];
            }
            #pragma unroll
            for (int j = 0; j < 4; j++) {
                const uint32_t* wr = &ws[buf][8 * s + q][wn * 32 + 8 * j + g];
                b[j][0] = wr[0];
                b[j][1] = wr[4 * WS_STR];
            }
            #pragma unroll
            for (int i = 0; i < 2; i++)
                #pragma unroll
                for (int j = 0; j < 4; j++)
                    asm("mma.sync.aligned.m16n8k8.row.col.f32.tf32.tf32.f32 "
                        "{%0,%1,%2,%3}, {%4,%5,%6,%7}, {%8,%9}, {%0,%1,%2,%3};"
                        : "+f"(acc[i][j][0]), "+f"(acc[i][j][1]),
                          "+f"(acc[i][j][2]), "+f"(acc[i][j][3])
                        : "r"(a[i][0]), "r"(a[i][1]), "r"(a[i][2]), "r"(a[i][3]),
                          "r"(b[j][0]), "r"(b[j][1]));
        }

        if (kt + 1 < NKT) {
            const int nb = buf ^ 1;
            *(uint4*)&xs[nb][arow][akl]      = make_uint4(f2tf(xf0.x), f2tf(xf0.y), f2tf(xf0.z), f2tf(xf0.w));
            *(uint4*)&xs[nb][arow + 64][akl] = make_uint4(f2tf(xf1.x), f2tf(xf1.y), f2tf(xf1.z), f2tf(xf1.w));
            *(uint4*)&ws[nb][wk][wn4]        = make_uint4(f2tf(wf.x),  f2tf(wf.y),  f2tf(wf.z),  f2tf(wf.w));
            __syncthreads();
        }
    }

    #pragma unroll
    for (int i = 0; i < 2; i++) {
        const int row = block_m + wm * 32 + 16 * i + g;
        #pragma unroll
        for (int j = 0; j < 4; j++) {
            const int col = wn * 32 + 8 * j + 2 * q;
            if (row < N_NODES)
                *(float2*)(g_h + (size_t)row * OUT_F + col) =
                    make_float2(acc[i][j][0], acc[i][j][1]);
            if (row + 8 < N_NODES)
                *(float2*)(g_h + (size_t)(row + 8) * OUT_F + col) =
                    make_float2(acc[i][j][2], acc[i][j][3]);
        }
    }
}

// ---------------------------------------------------------------------------
// Kernel 2: zero the per-node counters
// ---------------------------------------------------------------------------
__global__ void zero_kernel()
{
    const int t = blockIdx.x * blockDim.x + threadIdx.x;
    if (t < N_NODES) g_cnt[t] = 0;
}

// ---------------------------------------------------------------------------
// Kernel 3: reorder edges into per-dst buckets: bucket[dst][i] = (src, w)
// ---------------------------------------------------------------------------
__global__ void reorder_kernel(const float* __restrict__ ew,
                               const int* __restrict__ esrc,
                               const int* __restrict__ edst)
{
    const int e = blockIdx.x * blockDim.x + threadIdx.x;
    if (e >= N_EDGES) return;
    const int dst = __ldg(&edst[e]);
    const int src = __ldg(&esrc[e]);
    const float w = __ldg(&ew[e]);
    int pos = atomicAdd(&g_cnt[dst], 1);
    pos = min(pos, CAP - 1);        // safety clamp (statistically unreachable)
    g_bucket[(size_t)dst * CAP + pos] = make_uint2((uint32_t)src, __float_as_uint(w));
}

// ---------------------------------------------------------------------------
// Kernel 4: gather — one warp per node.
//   out[n] = bias + sum_i w_i * h[src_i].  No float atomics, no init pass.
// ---------------------------------------------------------------------------
__global__ void __launch_bounds__(256) gather_kernel(
    float* __restrict__ out, const float* __restrict__ bias)
{
    const int warp = (blockIdx.x * blockDim.x + threadIdx.x) >> 5;
    const int lane = threadIdx.x & 31;
    if (warp >= N_NODES) return;

    const int cnt = min(g_cnt[warp], CAP);
    const uint2* bk = g_bucket + (size_t)warp * CAP;

    float2 acc0 = make_float2(0.f, 0.f);
    float2 acc1 = make_float2(0.f, 0.f);

    int i = 0;
    // unroll-by-2 for MLP
    for (; i + 2 <= cnt; i += 2) {
        const uint2 e0 = __ldg(&bk[i]);
        const uint2 e1 = __ldg(&bk[i + 1]);
        const float w0 = __uint_as_float(e0.y);
        const float w1 = __uint_as_float(e1.y);
        const float2 h0 = __ldg((const float2*)(g_h + (size_t)e0.x * OUT_F + lane * 2));
        const float2 h1 = __ldg((const float2*)(g_h + (size_t)e1.x * OUT_F + lane * 2));
        acc0.x = fmaf(w0, h0.x, acc0.x); acc0.y = fmaf(w0, h0.y, acc0.y);
        acc1.x = fmaf(w1, h1.x, acc1.x); acc1.y = fmaf(w1, h1.y, acc1.y);
    }
    if (i < cnt) {
        const uint2 e0 = __ldg(&bk[i]);
        const float w0 = __uint_as_float(e0.y);
        const float2 h0 = __ldg((const float2*)(g_h + (size_t)e0.x * OUT_F + lane * 2));
        acc0.x = fmaf(w0, h0.x, acc0.x); acc0.y = fmaf(w0, h0.y, acc0.y);
    }

    const float2 b = __ldg((const float2*)(bias + lane * 2));
    float2 r;
    r.x = acc0.x + acc1.x + b.x;
    r.y = acc0.y + acc1.y + b.y;
    *(float2*)(out + (size_t)warp * OUT_F + lane * 2) = r;
}

// ---------------------------------------------------------------------------
// inputs (metadata order): x, weight, bias, edge_weight, edge_src, edge_dst
// ---------------------------------------------------------------------------
extern "C" void kernel_launch(void* const* d_in, const int* in_sizes, int n_in,
                              void* d_out, int out_size)
{
    const float* x      = (const float*)d_in[0];
    const float* weight = (const float*)d_in[1];
    const float* bias   = (const float*)d_in[2];
    const float* ew     = (const float*)d_in[3];
    const int*   esrc   = (const int*)d_in[4];
    const int*   edst   = (const int*)d_in[5];
    float* out = (float*)d_out;

    // 1) reset counters
    zero_kernel<<<(N_NODES + 255) / 256, 256>>>();

    // 2) bucket edges by dst
    reorder_kernel<<<(N_EDGES + 255) / 256, 256>>>(ew, esrc, edst);

    // 3) h = x @ W   (mma.sync tf32)
    gemm_kernel<<<(N_NODES + BM - 1) / BM, 256>>>(x, weight);

    // 4) gather per node: out = bias + sum w*h[src]
    {
        const int warps_per_block = 256 / 32;
        const int grid = (N_NODES + warps_per_block - 1) / warps_per_block;
        gather_kernel<<<grid, 256>>>(out, bias);
    }
}

// round 8
// speedup vs baseline: 1.9704x; 1.0083x over previous
#include <cuda_runtime.h>
#include <stdint.h>

#define N_NODES 50000
#define N_EDGES 800000
#define IN_F    256
#define OUT_F   64
#define CAP     128           // bucket capacity per node (avg degree 16)

// Device scratch (no allocs allowed)
__device__ float g_h[N_NODES * OUT_F];              // 12.8 MB: h = x @ W
__device__ int   g_cnt[N_NODES];                    // per-dst edge counts
__device__ uint2 g_bucket[(size_t)N_NODES * CAP];   // 51.2 MB: (src, w_bits)

__device__ __forceinline__ uint32_t f2tf(float f) {
    uint32_t r;
    asm("cvt.rna.tf32.f32 %0, %1;" : "=r"(r) : "f"(f));
    return r;
}

// ---------------------------------------------------------------------------
// Kernel 1: h = x @ W via warp-level mma.sync tf32 (m16n8k8).  (round-6 proven)
// ---------------------------------------------------------------------------
#define BM 128
#define BK 16
#define XS_STR 20
#define WS_STR 72

__global__ void __launch_bounds__(256, 3) gemm_kernel(
    const float* __restrict__ x, const float* __restrict__ w)
{
    __shared__ __align__(16) uint32_t xs[2][BM][XS_STR];  // A tile (tf32 bits), [row][k]
    __shared__ __align__(16) uint32_t ws[2][BK][WS_STR];  // W tile (tf32 bits), [k][n]

    const int tid  = threadIdx.x;
    const int wid  = tid >> 5;
    const int lane = tid & 31;
    const int wm = wid >> 1;
    const int wn = wid & 1;
    const int g  = lane >> 2;
    const int q  = lane & 3;
    const int block_m = blockIdx.x * BM;

    const int arow = tid >> 2;
    const int akl  = (tid & 3) << 2;
    const int gr0 = min(block_m + arow,      N_NODES - 1);
    const int gr1 = min(block_m + arow + 64, N_NODES - 1);
    const float* xp0 = x + (size_t)gr0 * IN_F + akl;
    const float* xp1 = x + (size_t)gr1 * IN_F + akl;

    const int wk  = tid >> 4;
    const int wn4 = (tid & 15) << 2;
    const float* wp = w + (size_t)wk * OUT_F + wn4;

    float acc[2][4][4];
    #pragma unroll
    for (int i = 0; i < 2; i++)
        #pragma unroll
        for (int j = 0; j < 4; j++)
            #pragma unroll
            for (int r = 0; r < 4; r++) acc[i][j][r] = 0.f;

    float4 xf0 = *(const float4*)xp0;
    float4 xf1 = *(const float4*)xp1;
    float4 wf  = *(const float4*)wp;

    *(uint4*)&xs[0][arow][akl]      = make_uint4(f2tf(xf0.x), f2tf(xf0.y), f2tf(xf0.z), f2tf(xf0.w));
    *(uint4*)&xs[0][arow + 64][akl] = make_uint4(f2tf(xf1.x), f2tf(xf1.y), f2tf(xf1.z), f2tf(xf1.w));
    *(uint4*)&ws[0][wk][wn4]        = make_uint4(f2tf(wf.x),  f2tf(wf.y),  f2tf(wf.z),  f2tf(wf.w));
    __syncthreads();

    const int NKT = IN_F / BK;

    #pragma unroll 1
    for (int kt = 0; kt < NKT; kt++) {
        const int buf = kt & 1;

        if (kt + 1 < NKT) {
            const int k0 = (kt + 1) * BK;
            xf0 = *(const float4*)(xp0 + k0);
            xf1 = *(const float4*)(xp1 + k0);
            wf  = *(const float4*)(wp + (size_t)k0 * OUT_F);
        }

        #pragma unroll
        for (int s = 0; s < 2; s++) {
            uint32_t a[2][4], b[4][2];
            #pragma unroll
            for (int i = 0; i < 2; i++) {
                const uint32_t* xr  = &xs[buf][wm * 32 + 16 * i + g][8 * s + q];
                const uint32_t* xr8 = xr + 8 * XS_STR;
                a[i][0] = xr[0];  a[i][2] = xr[4];
                a[i][1] = xr8[0]; a[i][3] = xr8[4];
            }
            #pragma unroll
            for (int j = 0; j < 4; j++) {
                const uint32_t* wr = &ws[buf][8 * s + q][wn * 32 + 8 * j + g];
                b[j][0] = wr[0];
                b[j][1] = wr[4 * WS_STR];
            }
            #pragma unroll
            for (int i = 0; i < 2; i++)
                #pragma unroll
                for (int j = 0; j < 4; j++)
                    asm("mma.sync.aligned.m16n8k8.row.col.f32.tf32.tf32.f32 "
                        "{%0,%1,%2,%3}, {%4,%5,%6,%7}, {%8,%9}, {%0,%1,%2,%3};"
                        : "+f"(acc[i][j][0]), "+f"(acc[i][j][1]),
                          "+f"(acc[i][j][2]), "+f"(acc[i][j][3])
                        : "r"(a[i][0]), "r"(a[i][1]), "r"(a[i][2]), "r"(a[i][3]),
                          "r"(b[j][0]), "r"(b[j][1]));
        }

        if (kt + 1 < NKT) {
            const int nb = buf ^ 1;
            *(uint4*)&xs[nb][arow][akl]      = make_uint4(f2tf(xf0.x), f2tf(xf0.y), f2tf(xf0.z), f2tf(xf0.w));
            *(uint4*)&xs[nb][arow + 64][akl] = make_uint4(f2tf(xf1.x), f2tf(xf1.y), f2tf(xf1.z), f2tf(xf1.w));
            *(uint4*)&ws[nb][wk][wn4]        = make_uint4(f2tf(wf.x),  f2tf(wf.y),  f2tf(wf.z),  f2tf(wf.w));
            __syncthreads();
        }
    }

    #pragma unroll
    for (int i = 0; i < 2; i++) {
        const int row = block_m + wm * 32 + 16 * i + g;
        #pragma unroll
        for (int j = 0; j < 4; j++) {
            const int col = wn * 32 + 8 * j + 2 * q;
            if (row < N_NODES)
                *(float2*)(g_h + (size_t)row * OUT_F + col) =
                    make_float2(acc[i][j][0], acc[i][j][1]);
            if (row + 8 < N_NODES)
                *(float2*)(g_h + (size_t)(row + 8) * OUT_F + col) =
                    make_float2(acc[i][j][2], acc[i][j][3]);
        }
    }
}

// ---------------------------------------------------------------------------
// Kernel 2: zero the per-node counters
// ---------------------------------------------------------------------------
__global__ void zero_kernel()
{
    const int t = blockIdx.x * blockDim.x + threadIdx.x;
    if (t < N_NODES) g_cnt[t] = 0;
}

// ---------------------------------------------------------------------------
// Kernel 3: reorder edges into per-dst buckets: bucket[dst][i] = (src, w)
// ---------------------------------------------------------------------------
__global__ void reorder_kernel(const float* __restrict__ ew,
                               const int* __restrict__ esrc,
                               const int* __restrict__ edst)
{
    const int e = blockIdx.x * blockDim.x + threadIdx.x;
    if (e >= N_EDGES) return;
    const int dst = __ldg(&edst[e]);
    const int src = __ldg(&esrc[e]);
    const float w = __ldg(&ew[e]);
    int pos = atomicAdd(&g_cnt[dst], 1);
    pos = min(pos, CAP - 1);        // safety clamp (statistically unreachable)
    g_bucket[(size_t)dst * CAP + pos] = make_uint2((uint32_t)src, __float_as_uint(w));
}

// ---------------------------------------------------------------------------
// Kernel 4: gather — one warp per node, MLP-maximized.
//   One warp-wide LDG grabs 32 bucket entries; h-row loads are then issued in
//   independent batches of 8 (zero-filled tail lanes contribute w=0).
// ---------------------------------------------------------------------------
__global__ void __launch_bounds__(256) gather_kernel(
    float* __restrict__ out, const float* __restrict__ bias)
{
    const int warp = (blockIdx.x * blockDim.x + threadIdx.x) >> 5;
    const int lane = threadIdx.x & 31;
    if (warp >= N_NODES) return;

    const int cnt = min(__ldg(&g_cnt[warp]), CAP);
    const uint2* bk = g_bucket + (size_t)warp * CAP;

    float2 acc[4];
    #pragma unroll
    for (int i = 0; i < 4; i++) acc[i] = make_float2(0.f, 0.f);

    #pragma unroll 1
    for (int base = 0; base < cnt; base += 32) {
        // 32 bucket entries in one warp-wide load; zero-fill past cnt
        uint2 ev = (base + lane < cnt) ? __ldg(&bk[base + lane])
                                       : make_uint2(0u, 0u);
        #pragma unroll
        for (int jb = 0; jb < 32; jb += 8) {
            if (base + jb >= cnt) break;          // uniform per-warp branch
            float wv[8];
            float2 hv[8];
            #pragma unroll
            for (int k = 0; k < 8; k++) {
                const uint32_t s  = __shfl_sync(0xffffffffu, ev.x, jb + k);
                const uint32_t wb = __shfl_sync(0xffffffffu, ev.y, jb + k);
                wv[k] = __uint_as_float(wb);
                hv[k] = __ldg((const float2*)(g_h + (size_t)s * OUT_F + lane * 2));
            }
            #pragma unroll
            for (int k = 0; k < 8; k++) {
                acc[k & 3].x = fmaf(wv[k], hv[k].x, acc[k & 3].x);
                acc[k & 3].y = fmaf(wv[k], hv[k].y, acc[k & 3].y);
            }
        }
    }

    const float2 b = __ldg((const float2*)(bias + lane * 2));
    float2 r;
    r.x = acc[0].x + acc[1].x + acc[2].x + acc[3].x + b.x;
    r.y = acc[0].y + acc[1].y + acc[2].y + acc[3].y + b.y;
    *(float2*)(out + (size_t)warp * OUT_F + lane * 2) = r;
}

// ---------------------------------------------------------------------------
// inputs (metadata order): x, weight, bias, edge_weight, edge_src, edge_dst
// ---------------------------------------------------------------------------
extern "C" void kernel_launch(void* const* d_in, const int* in_sizes, int n_in,
                              void* d_out, int out_size)
{
    const float* x      = (const float*)d_in[0];
    const float* weight = (const float*)d_in[1];
    const float* bias   = (const float*)d_in[2];
    const float* ew     = (const float*)d_in[3];
    const int*   esrc   = (const int*)d_in[4];
    const int*   edst   = (const int*)d_in[5];
    float* out = (float*)d_out;

    // 1) reset counters
    zero_kernel<<<(N_NODES + 255) / 256, 256>>>();

    // 2) bucket edges by dst
    reorder_kernel<<<(N_EDGES + 255) / 256, 256>>>(ew, esrc, edst);

    // 3) h = x @ W   (mma.sync tf32)
    gemm_kernel<<<(N_NODES + BM - 1) / BM, 256>>>(x, weight);

    // 4) gather per node: out = bias + sum w*h[src]
    {
        const int warps_per_block = 256 / 32;
        const int grid = (N_NODES + warps_per_block - 1) / warps_per_block;
        gather_kernel<<<grid, 256>>>(out, bias);
    }
}

// round 9
// speedup vs baseline: 2.0828x; 1.0570x over previous
#include <cuda_runtime.h>
#include <cuda_fp16.h>
#include <stdint.h>

#define N_NODES 50000
#define N_EDGES 800000
#define IN_F    256
#define OUT_F   64
#define CAP     128           // bucket capacity per node (avg degree 16)

// Device scratch (no allocs allowed)
__device__ __half g_h[N_NODES * OUT_F];             // 6.4 MB: h = x @ W (fp16)
__device__ int    g_cnt[N_NODES];                   // per-dst edge counts
__device__ uint2  g_bucket[(size_t)N_NODES * CAP];  // 51.2 MB: (src, w_bits)

__device__ __forceinline__ uint32_t f2tf(float f) {
    uint32_t r;
    asm("cvt.rna.tf32.f32 %0, %1;" : "=r"(r) : "f"(f));
    return r;
}
__device__ __forceinline__ void cp16(uint32_t dst, const void* src) {
    asm volatile("cp.async.ca.shared.global [%0], [%1], 16;" :: "r"(dst), "l"(src));
}

// ---------------------------------------------------------------------------
// Kernel 1: h = x @ W via mma.sync tf32, 3-stage cp.async pipeline.
//   BM=128, BK=16, 256 threads = 8 warps (4x2 warp grid, 32x32 per warp).
//   Raw fp32 staged in smem; cvt.rna.tf32 applied at fragment load.
// ---------------------------------------------------------------------------
#define BM 128
#define BK 16
#define XS_STR 20
#define WS_STR 72
#define STAGES 3

__global__ void __launch_bounds__(256) gemm_kernel(
    const float* __restrict__ x, const float* __restrict__ w)
{
    __shared__ __align__(16) float xs[STAGES][BM][XS_STR];  // A tiles [row][k]
    __shared__ __align__(16) float ws[STAGES][BK][WS_STR];  // W tiles [k][n]

    const int tid  = threadIdx.x;
    const int wid  = tid >> 5;
    const int lane = tid & 31;
    const int wm = wid >> 1;
    const int wn = wid & 1;
    const int g  = lane >> 2;
    const int q  = lane & 3;
    const int block_m = blockIdx.x * BM;

    // A copy map: 512 x 16B chunks, 2 per thread (rows tid>>2 and +64)
    const int arow = tid >> 2;               // 0..63
    const int akc  = (tid & 3) << 2;         // k offset 0,4,8,12
    const int gr0 = min(block_m + arow,      N_NODES - 1);
    const int gr1 = min(block_m + arow + 64, N_NODES - 1);
    const float* xp0 = x + (size_t)gr0 * IN_F + akc;
    const float* xp1 = x + (size_t)gr1 * IN_F + akc;

    // W copy map: 256 x 16B chunks, 1 per thread
    const int wk  = tid >> 4;                // 0..15
    const int wn4 = (tid & 15) << 2;         // 0..60
    const float* wp = w + (size_t)wk * OUT_F + wn4;

    const int NKT = IN_F / BK;   // 16

    // per-stage smem dst addresses (u32)
    uint32_t xs_dst[STAGES], ws_dst[STAGES];
    #pragma unroll
    for (int s = 0; s < STAGES; s++) {
        xs_dst[s] = (uint32_t)__cvta_generic_to_shared(&xs[s][arow][akc]);
        ws_dst[s] = (uint32_t)__cvta_generic_to_shared(&ws[s][wk][wn4]);
    }
    const uint32_t xs_row64 = 64 * XS_STR * 4;   // byte offset of row+64

    float acc[2][4][4];
    #pragma unroll
    for (int i = 0; i < 2; i++)
        #pragma unroll
        for (int j = 0; j < 4; j++)
            #pragma unroll
            for (int r = 0; r < 4; r++) acc[i][j][r] = 0.f;

    // ---- prologue: issue tiles 0 and 1 ----
    #pragma unroll
    for (int t = 0; t < 2; t++) {
        const int k0 = t * BK;
        cp16(xs_dst[t],            xp0 + k0);
        cp16(xs_dst[t] + xs_row64, xp1 + k0);
        cp16(ws_dst[t],            wp + (size_t)k0 * OUT_F);
        asm volatile("cp.async.commit_group;");
    }

    #pragma unroll 1
    for (int kt = 0; kt < NKT; kt++) {
        if (kt < NKT - 1) {
            asm volatile("cp.async.wait_group 1;");
        } else {
            asm volatile("cp.async.wait_group 0;");
        }
        __syncthreads();

        // issue tile kt+2 into buffer (kt+2)%STAGES (freed by compute(kt-1))
        if (kt + 2 < NKT) {
            const int nb = (kt + 2) % STAGES;
            const int k0 = (kt + 2) * BK;
            cp16(xs_dst[nb],            xp0 + k0);
            cp16(xs_dst[nb] + xs_row64, xp1 + k0);
            cp16(ws_dst[nb],            wp + (size_t)k0 * OUT_F);
            asm volatile("cp.async.commit_group;");
        }

        // ---- compute tile kt ----
        const int buf = kt % STAGES;
        #pragma unroll
        for (int s = 0; s < 2; s++) {
            uint32_t a[2][4], b[4][2];
            #pragma unroll
            for (int i = 0; i < 2; i++) {
                const float* xr  = &xs[buf][wm * 32 + 16 * i + g][8 * s + q];
                const float* xr8 = xr + 8 * XS_STR;
                a[i][0] = f2tf(xr[0]);  a[i][2] = f2tf(xr[4]);
                a[i][1] = f2tf(xr8[0]); a[i][3] = f2tf(xr8[4]);
            }
            #pragma unroll
            for (int j = 0; j < 4; j++) {
                const float* wr = &ws[buf][8 * s + q][wn * 32 + 8 * j + g];
                b[j][0] = f2tf(wr[0]);
                b[j][1] = f2tf(wr[4 * WS_STR]);
            }
            #pragma unroll
            for (int i = 0; i < 2; i++)
                #pragma unroll
                for (int j = 0; j < 4; j++)
                    asm("mma.sync.aligned.m16n8k8.row.col.f32.tf32.tf32.f32 "
                        "{%0,%1,%2,%3}, {%4,%5,%6,%7}, {%8,%9}, {%0,%1,%2,%3};"
                        : "+f"(acc[i][j][0]), "+f"(acc[i][j][1]),
                          "+f"(acc[i][j][2]), "+f"(acc[i][j][3])
                        : "r"(a[i][0]), "r"(a[i][1]), "r"(a[i][2]), "r"(a[i][3]),
                          "r"(b[j][0]), "r"(b[j][1]));
        }
    }

    // ---- epilogue: store fp16 h (cols 2q,2q+1 of each mma tile as one half2) ----
    #pragma unroll
    for (int i = 0; i < 2; i++) {
        const int row = block_m + wm * 32 + 16 * i + g;
        #pragma unroll
        for (int j = 0; j < 4; j++) {
            const int col = wn * 32 + 8 * j + 2 * q;
            if (row < N_NODES)
                *(__half2*)(g_h + (size_t)row * OUT_F + col) =
                    __float22half2_rn(make_float2(acc[i][j][0], acc[i][j][1]));
            if (row + 8 < N_NODES)
                *(__half2*)(g_h + (size_t)(row + 8) * OUT_F + col) =
                    __float22half2_rn(make_float2(acc[i][j][2], acc[i][j][3]));
        }
    }
}

// ---------------------------------------------------------------------------
// Kernel 2: zero the per-node counters
// ---------------------------------------------------------------------------
__global__ void zero_kernel()
{
    const int t = blockIdx.x * blockDim.x + threadIdx.x;
    if (t < N_NODES) g_cnt[t] = 0;
}

// ---------------------------------------------------------------------------
// Kernel 3: reorder edges into per-dst buckets: bucket[dst][i] = (src, w)
// ---------------------------------------------------------------------------
__global__ void reorder_kernel(const float* __restrict__ ew,
                               const int* __restrict__ esrc,
                               const int* __restrict__ edst)
{
    const int e = blockIdx.x * blockDim.x + threadIdx.x;
    if (e >= N_EDGES) return;
    const int dst = __ldg(&edst[e]);
    const int src = __ldg(&esrc[e]);
    const float w = __ldg(&ew[e]);
    int pos = atomicAdd(&g_cnt[dst], 1);
    pos = min(pos, CAP - 1);        // safety clamp (statistically unreachable)
    g_bucket[(size_t)dst * CAP + pos] = make_uint2((uint32_t)src, __float_as_uint(w));
}

// ---------------------------------------------------------------------------
// Kernel 4: gather — one warp per node; fp16 h rows (128 B per edge).
// ---------------------------------------------------------------------------
__global__ void __launch_bounds__(256) gather_kernel(
    float* __restrict__ out, const float* __restrict__ bias)
{
    const int warp = (blockIdx.x * blockDim.x + threadIdx.x) >> 5;
    const int lane = threadIdx.x & 31;
    if (warp >= N_NODES) return;

    const int cnt = min(__ldg(&g_cnt[warp]), CAP);
    const uint2* bk = g_bucket + (size_t)warp * CAP;

    float2 acc[4];
    #pragma unroll
    for (int i = 0; i < 4; i++) acc[i] = make_float2(0.f, 0.f);

    #pragma unroll 1
    for (int base = 0; base < cnt; base += 32) {
        uint2 ev = (base + lane < cnt) ? __ldg(&bk[base + lane])
                                       : make_uint2(0u, 0u);
        #pragma unroll
        for (int jb = 0; jb < 32; jb += 8) {
            if (base + jb >= cnt) break;          // uniform per-warp branch
            float   wv[8];
            __half2 hv[8];
            #pragma unroll
            for (int k = 0; k < 8; k++) {
                const uint32_t s  = __shfl_sync(0xffffffffu, ev.x, jb + k);
                const uint32_t wb = __shfl_sync(0xffffffffu, ev.y, jb + k);
                wv[k] = __uint_as_float(wb);
                hv[k] = __ldg((const __half2*)(g_h + (size_t)s * OUT_F + lane * 2));
            }
            #pragma unroll
            for (int k = 0; k < 8; k++) {
                const float2 h = __half22float2(hv[k]);
                acc[k & 3].x = fmaf(wv[k], h.x, acc[k & 3].x);
                acc[k & 3].y = fmaf(wv[k], h.y, acc[k & 3].y);
            }
        }
    }

    const float2 b = __ldg((const float2*)(bias + lane * 2));
    float2 r;
    r.x = acc[0].x + acc[1].x + acc[2].x + acc[3].x + b.x;
    r.y = acc[0].y + acc[1].y + acc[2].y + acc[3].y + b.y;
    *(float2*)(out + (size_t)warp * OUT_F + lane * 2) = r;
}

// ---------------------------------------------------------------------------
// inputs (metadata order): x, weight, bias, edge_weight, edge_src, edge_dst
// ---------------------------------------------------------------------------
extern "C" void kernel_launch(void* const* d_in, const int* in_sizes, int n_in,
                              void* d_out, int out_size)
{
    const float* x      = (const float*)d_in[0];
    const float* weight = (const float*)d_in[1];
    const float* bias   = (const float*)d_in[2];
    const float* ew     = (const float*)d_in[3];
    const int*   esrc   = (const int*)d_in[4];
    const int*   edst   = (const int*)d_in[5];
    float* out = (float*)d_out;

    // 1) reset counters
    zero_kernel<<<(N_NODES + 255) / 256, 256>>>();

    // 2) bucket edges by dst
    reorder_kernel<<<(N_EDGES + 255) / 256, 256>>>(ew, esrc, edst);

    // 3) h = x @ W   (mma.sync tf32, cp.async pipeline)
    gemm_kernel<<<(N_NODES + BM - 1) / BM, 256>>>(x, weight);

    // 4) gather per node: out = bias + sum w*h[src]
    {
        const int warps_per_block = 256 / 32;
        const int grid = (N_NODES + warps_per_block - 1) / warps_per_block;
        gather_kernel<<<grid, 256>>>(out, bias);
    }
}

// round 10
// speedup vs baseline: 2.2268x; 1.0692x over previous
#include <cuda_runtime.h>
#include <cuda_fp16.h>
#include <stdint.h>

#define N_NODES 50000
#define N_EDGES 800000
#define IN_F    256
#define OUT_F   64
#define CAP     128           // bucket capacity per node (avg degree 16)

// Device scratch (no allocs allowed)
__device__ __half g_h[N_NODES * OUT_F];             // 6.4 MB: h = x @ W (fp16)
__device__ int    g_cnt[N_NODES];                   // per-dst edge counts
__device__ uint2  g_bucket[(size_t)N_NODES * CAP];  // 51.2 MB: (src, w_bits)

__device__ __forceinline__ uint32_t f2tf(float f) {
    uint32_t r;
    asm("cvt.rna.tf32.f32 %0, %1;" : "=r"(r) : "f"(f));
    return r;
}
__device__ __forceinline__ void cp16(uint32_t dst, const void* src) {
    asm volatile("cp.async.ca.shared.global [%0], [%1], 16;" :: "r"(dst), "l"(src));
}

// ---------------------------------------------------------------------------
// Kernel 1: h = x @ W via mma.sync tf32, 3-stage cp.async pipeline. (round-9)
// ---------------------------------------------------------------------------
#define BM 128
#define BK 16
#define XS_STR 20
#define WS_STR 72
#define STAGES 3

__global__ void __launch_bounds__(256) gemm_kernel(
    const float* __restrict__ x, const float* __restrict__ w)
{
    __shared__ __align__(16) float xs[STAGES][BM][XS_STR];  // A tiles [row][k]
    __shared__ __align__(16) float ws[STAGES][BK][WS_STR];  // W tiles [k][n]

    const int tid  = threadIdx.x;
    const int wid  = tid >> 5;
    const int lane = tid & 31;
    const int wm = wid >> 1;
    const int wn = wid & 1;
    const int g  = lane >> 2;
    const int q  = lane & 3;
    const int block_m = blockIdx.x * BM;

    const int arow = tid >> 2;
    const int akc  = (tid & 3) << 2;
    const int gr0 = min(block_m + arow,      N_NODES - 1);
    const int gr1 = min(block_m + arow + 64, N_NODES - 1);
    const float* xp0 = x + (size_t)gr0 * IN_F + akc;
    const float* xp1 = x + (size_t)gr1 * IN_F + akc;

    const int wk  = tid >> 4;
    const int wn4 = (tid & 15) << 2;
    const float* wp = w + (size_t)wk * OUT_F + wn4;

    const int NKT = IN_F / BK;   // 16

    uint32_t xs_dst[STAGES], ws_dst[STAGES];
    #pragma unroll
    for (int s = 0; s < STAGES; s++) {
        xs_dst[s] = (uint32_t)__cvta_generic_to_shared(&xs[s][arow][akc]);
        ws_dst[s] = (uint32_t)__cvta_generic_to_shared(&ws[s][wk][wn4]);
    }
    const uint32_t xs_row64 = 64 * XS_STR * 4;

    float acc[2][4][4];
    #pragma unroll
    for (int i = 0; i < 2; i++)
        #pragma unroll
        for (int j = 0; j < 4; j++)
            #pragma unroll
            for (int r = 0; r < 4; r++) acc[i][j][r] = 0.f;

    #pragma unroll
    for (int t = 0; t < 2; t++) {
        const int k0 = t * BK;
        cp16(xs_dst[t],            xp0 + k0);
        cp16(xs_dst[t] + xs_row64, xp1 + k0);
        cp16(ws_dst[t],            wp + (size_t)k0 * OUT_F);
        asm volatile("cp.async.commit_group;");
    }

    #pragma unroll 1
    for (int kt = 0; kt < NKT; kt++) {
        if (kt < NKT - 1) {
            asm volatile("cp.async.wait_group 1;");
        } else {
            asm volatile("cp.async.wait_group 0;");
        }
        __syncthreads();

        if (kt + 2 < NKT) {
            const int nb = (kt + 2) % STAGES;
            const int k0 = (kt + 2) * BK;
            cp16(xs_dst[nb],            xp0 + k0);
            cp16(xs_dst[nb] + xs_row64, xp1 + k0);
            cp16(ws_dst[nb],            wp + (size_t)k0 * OUT_F);
            asm volatile("cp.async.commit_group;");
        }

        const int buf = kt % STAGES;
        #pragma unroll
        for (int s = 0; s < 2; s++) {
            uint32_t a[2][4], b[4][2];
            #pragma unroll
            for (int i = 0; i < 2; i++) {
                const float* xr  = &xs[buf][wm * 32 + 16 * i + g][8 * s + q];
                const float* xr8 = xr + 8 * XS_STR;
                a[i][0] = f2tf(xr[0]);  a[i][2] = f2tf(xr[4]);
                a[i][1] = f2tf(xr8[0]); a[i][3] = f2tf(xr8[4]);
            }
            #pragma unroll
            for (int j = 0; j < 4; j++) {
                const float* wr = &ws[buf][8 * s + q][wn * 32 + 8 * j + g];
                b[j][0] = f2tf(wr[0]);
                b[j][1] = f2tf(wr[4 * WS_STR]);
            }
            #pragma unroll
            for (int i = 0; i < 2; i++)
                #pragma unroll
                for (int j = 0; j < 4; j++)
                    asm("mma.sync.aligned.m16n8k8.row.col.f32.tf32.tf32.f32 "
                        "{%0,%1,%2,%3}, {%4,%5,%6,%7}, {%8,%9}, {%0,%1,%2,%3};"
                        : "+f"(acc[i][j][0]), "+f"(acc[i][j][1]),
                          "+f"(acc[i][j][2]), "+f"(acc[i][j][3])
                        : "r"(a[i][0]), "r"(a[i][1]), "r"(a[i][2]), "r"(a[i][3]),
                          "r"(b[j][0]), "r"(b[j][1]));
        }
    }

    #pragma unroll
    for (int i = 0; i < 2; i++) {
        const int row = block_m + wm * 32 + 16 * i + g;
        #pragma unroll
        for (int j = 0; j < 4; j++) {
            const int col = wn * 32 + 8 * j + 2 * q;
            if (row < N_NODES)
                *(__half2*)(g_h + (size_t)row * OUT_F + col) =
                    __float22half2_rn(make_float2(acc[i][j][0], acc[i][j][1]));
            if (row + 8 < N_NODES)
                *(__half2*)(g_h + (size_t)(row + 8) * OUT_F + col) =
                    __float22half2_rn(make_float2(acc[i][j][2], acc[i][j][3]));
        }
    }
}

// ---------------------------------------------------------------------------
// Kernel 2: zero the per-node counters
// ---------------------------------------------------------------------------
__global__ void zero_kernel()
{
    const int t = blockIdx.x * blockDim.x + threadIdx.x;
    if (t < N_NODES) g_cnt[t] = 0;
}

// ---------------------------------------------------------------------------
// Kernel 3: reorder edges into per-dst buckets: bucket[dst][i] = (src, w)
// ---------------------------------------------------------------------------
__global__ void reorder_kernel(const float* __restrict__ ew,
                               const int* __restrict__ esrc,
                               const int* __restrict__ edst)
{
    const int e = blockIdx.x * blockDim.x + threadIdx.x;
    if (e >= N_EDGES) return;
    const int dst = __ldg(&edst[e]);
    const int src = __ldg(&esrc[e]);
    const float w = __ldg(&ew[e]);
    int pos = atomicAdd(&g_cnt[dst], 1);
    pos = min(pos, CAP - 1);        // safety clamp (statistically unreachable)
    g_bucket[(size_t)dst * CAP + pos] = make_uint2((uint32_t)src, __float_as_uint(w));
}

// ---------------------------------------------------------------------------
// Kernel 4: gather — HALF-WARP per node (2 nodes/warp => 2x independent
//   memory chains per warp). Lane handles 4 fp16 features via one LDG.64;
//   one edge still touches exactly one 128-B line.
// ---------------------------------------------------------------------------
__global__ void __launch_bounds__(256) gather_kernel(
    float* __restrict__ out, const float* __restrict__ bias)
{
    const int gwarp = (blockIdx.x * blockDim.x + threadIdx.x) >> 5;
    const int lane  = threadIdx.x & 31;
    const int half  = lane >> 4;            // 0 or 1
    const int hl    = lane & 15;            // lane within half
    const int node  = gwarp * 2 + half;
    if (node >= N_NODES) return;

    const unsigned hmask = half ? 0xffff0000u : 0x0000ffffu;
    const int laneoff = half << 4;

    const int cnt = min(__ldg(&g_cnt[node]), CAP);
    const uint2* bk = g_bucket + (size_t)node * CAP;

    float acc[4] = {0.f, 0.f, 0.f, 0.f};

    #pragma unroll 1
    for (int base = 0; base < cnt; base += 16) {
        // 16 bucket entries per half-warp in one warp-wide load
        uint2 ev = (base + hl < cnt) ? __ldg(&bk[base + hl]) : make_uint2(0u, 0u);
        #pragma unroll
        for (int jb = 0; jb < 16; jb += 8) {
            if (base + jb >= cnt) break;      // uniform within the half-warp
            float wv[8];
            uint2 hv[8];
            #pragma unroll
            for (int k = 0; k < 8; k++) {
                const uint32_t s  = __shfl_sync(hmask, ev.x, laneoff + jb + k);
                const uint32_t wb = __shfl_sync(hmask, ev.y, laneoff + jb + k);
                wv[k] = __uint_as_float(wb);
                hv[k] = __ldg((const uint2*)(g_h + (size_t)s * OUT_F + hl * 4));
            }
            #pragma unroll
            for (int k = 0; k < 8; k++) {
                const float2 h0 = __half22float2(*(const __half2*)&hv[k].x);
                const float2 h1 = __half22float2(*(const __half2*)&hv[k].y);
                acc[0] = fmaf(wv[k], h0.x, acc[0]);
                acc[1] = fmaf(wv[k], h0.y, acc[1]);
                acc[2] = fmaf(wv[k], h1.x, acc[2]);
                acc[3] = fmaf(wv[k], h1.y, acc[3]);
            }
        }
    }

    const float4 b = __ldg((const float4*)(bias + hl * 4));
    float4 r = make_float4(acc[0] + b.x, acc[1] + b.y, acc[2] + b.z, acc[3] + b.w);
    *(float4*)(out + (size_t)node * OUT_F + hl * 4) = r;
}

// ---------------------------------------------------------------------------
// inputs (metadata order): x, weight, bias, edge_weight, edge_src, edge_dst
// ---------------------------------------------------------------------------
extern "C" void kernel_launch(void* const* d_in, const int* in_sizes, int n_in,
                              void* d_out, int out_size)
{
    const float* x      = (const float*)d_in[0];
    const float* weight = (const float*)d_in[1];
    const float* bias   = (const float*)d_in[2];
    const float* ew     = (const float*)d_in[3];
    const int*   esrc   = (const int*)d_in[4];
    const int*   edst   = (const int*)d_in[5];
    float* out = (float*)d_out;

    // 1) reset counters
    zero_kernel<<<(N_NODES + 255) / 256, 256>>>();

    // 2) bucket edges by dst
    reorder_kernel<<<(N_EDGES + 255) / 256, 256>>>(ew, esrc, edst);

    // 3) h = x @ W   (mma.sync tf32, cp.async pipeline)
    gemm_kernel<<<(N_NODES + BM - 1) / BM, 256>>>(x, weight);

    // 4) gather: 2 nodes per warp (half-warp each)
    {
        const int nodes_per_block = 2 * (256 / 32);     // 16
        const int grid = (N_NODES + nodes_per_block - 1) / nodes_per_block;
        gather_kernel<<<grid, 256>>>(out, bias);
    }
}